// round 1
// baseline (speedup 1.0000x reference)
#include <cuda_runtime.h>

// Problem constants (fixed by the reference)
#define BB 16
#define HH 768
#define WW 768
#define KK 512
#define HWSZ (HH * WW)          // 589824
#define TOTAL (BB * HWSZ)       // 9437184
#define VECS_PER_ROW (WW / 4)   // 192
#define TOTAL_VECS (TOTAL / 4)  // 2359296

// Global accumulators: [0] = l1 numerator, [1] = l2 numerator
__device__ double g_acc[2];

__global__ void zero_acc_kernel() {
    if (threadIdx.x < 2) g_acc[threadIdx.x] = 0.0;
}

__inline__ __device__ float warp_reduce(float v) {
    #pragma unroll
    for (int o = 16; o > 0; o >>= 1) v += __shfl_down_sync(0xffffffffu, v, o);
    return v;
}

// Bulk pass: per pixel accumulate pre_mask*err into s1 and mse_mask*err into s2.
__global__ void __launch_bounds__(256) main_reduce_kernel(
    const float* __restrict__ pre, const float* __restrict__ gt)
{
    float s1 = 0.f, s2 = 0.f;

    for (int vec = blockIdx.x * blockDim.x + threadIdx.x;
         vec < TOTAL_VECS;
         vec += gridDim.x * blockDim.x)
    {
        const int row = vec / VECS_PER_ROW;     // global row in [0, B*H)
        const int y   = row % HH;
        const int x0  = (vec % VECS_PER_ROW) * 4;
        const int base = row * WW + x0;         // == b*HW + y*W + x0

        const float4 c  = *reinterpret_cast<const float4*>(pre + base);
        const float4 g  = *reinterpret_cast<const float4*>(gt  + base);
        const float4 up = (y > 0)      ? *reinterpret_cast<const float4*>(pre + base - WW)
                                       : make_float4(0.f, 0.f, 0.f, 0.f);
        const float4 dn = (y < HH - 1) ? *reinterpret_cast<const float4*>(pre + base + WW)
                                       : make_float4(0.f, 0.f, 0.f, 0.f);
        const float lft = (x0 > 0)        ? __ldg(pre + base - 1) : 0.f;
        const float rgt = (x0 + 4 < WW)   ? __ldg(pre + base + 4) : 0.f;

        const float cv[4] = {c.x, c.y, c.z, c.w};
        const float gv[4] = {g.x, g.y, g.z, g.w};
        const float uv[4] = {up.x, up.y, up.z, up.w};
        const float dv[4] = {dn.x, dn.y, dn.z, dn.w};
        const float lv[4] = {lft, c.x, c.y, c.z};
        const float rv[4] = {c.y, c.z, c.w, rgt};

        #pragma unroll
        for (int i = 0; i < 4; i++) {
            const float d   = cv[i] - gv[i];
            const float err = d * d;
            const bool pm = (cv[i] > lv[i]) && (cv[i] > rv[i]) &&
                            (cv[i] > uv[i]) && (cv[i] > dv[i]);
            if (pm) s1 += err;
            s2 += (gv[i] > 0.f ? 5.f : 1.f) * err;
        }
    }

    // Block reduction (warp shuffle + shared)
    __shared__ float sh1[8], sh2[8];
    const int lane = threadIdx.x & 31;
    const int wid  = threadIdx.x >> 5;
    s1 = warp_reduce(s1);
    s2 = warp_reduce(s2);
    if (lane == 0) { sh1[wid] = s1; sh2[wid] = s2; }
    __syncthreads();
    if (wid == 0) {
        float v1 = (lane < 8) ? sh1[lane] : 0.f;
        float v2 = (lane < 8) ? sh2[lane] : 0.f;
        v1 = warp_reduce(v1);
        v2 = warp_reduce(v2);
        if (lane == 0) {
            atomicAdd(&g_acc[0], (double)v1);
            atomicAdd(&g_acc[1], (double)v2);
        }
    }
}

// gt-point correction: l1 += err*(1 - 2*pre_mask) at each UNIQUE gt coordinate.
// One block per batch, one thread per point; O(K^2) dedup keeps first occurrence.
__global__ void __launch_bounds__(KK) gt_correction_kernel(
    const float* __restrict__ pre, const float* __restrict__ gt,
    const int* __restrict__ cors)
{
    const int b = blockIdx.x;
    const int t = threadIdx.x;

    __shared__ int sx[KK];
    __shared__ int sy[KK];

    const int x = cors[(b * KK + t) * 2 + 0];
    const int y = cors[(b * KK + t) * 2 + 1];
    sx[t] = x;
    sy[t] = y;
    __syncthreads();

    bool dup = false;
    for (int j = 0; j < t; j++) {
        if (sx[j] == x && sy[j] == y) { dup = true; break; }
    }

    float contrib = 0.f;
    if (!dup) {
        const int base = b * HWSZ + y * WW + x;
        const float c = pre[base];
        const float l = (x > 0)      ? pre[base - 1]  : 0.f;
        const float r = (x < WW - 1) ? pre[base + 1]  : 0.f;
        const float u = (y > 0)      ? pre[base - WW] : 0.f;
        const float d = (y < HH - 1) ? pre[base + WW] : 0.f;
        const bool pm = (c > l) && (c > r) && (c > u) && (c > d);
        const float diff = c - gt[base];
        const float err  = diff * diff;
        contrib = err * (1.f - 2.f * (pm ? 1.f : 0.f));
    }

    // Block reduction
    __shared__ float sh[KK / 32];
    const int lane = t & 31;
    const int wid  = t >> 5;
    contrib = warp_reduce(contrib);
    if (lane == 0) sh[wid] = contrib;
    __syncthreads();
    if (wid == 0) {
        float v = (lane < KK / 32) ? sh[lane] : 0.f;
        v = warp_reduce(v);
        if (lane == 0) atomicAdd(&g_acc[0], (double)v);
    }
}

__global__ void finalize_kernel(float* __restrict__ out) {
    if (threadIdx.x == 0)
        out[0] = (float)((g_acc[0] + g_acc[1]) / (double)BB);
}

extern "C" void kernel_launch(void* const* d_in, const int* in_sizes, int n_in,
                              void* d_out, int out_size)
{
    const float* pre  = (const float*)d_in[0];
    const float* gt   = (const float*)d_in[1];
    const int*   cors = (const int*)d_in[2];
    float*       out  = (float*)d_out;

    zero_acc_kernel<<<1, 32>>>();

    const int threads = 256;
    const int blocks  = 148 * 8;   // grid-stride; ~2.4k double atomics total
    main_reduce_kernel<<<blocks, threads>>>(pre, gt);

    gt_correction_kernel<<<BB, KK>>>(pre, gt, cors);

    finalize_kernel<<<1, 32>>>(out);
}